// round 2
// baseline (speedup 1.0000x reference)
#include <cuda_runtime.h>

static constexpr int NN = 50000;
static constexpr int EE = 800000;

// ---------------- scratch (device globals; no allocation allowed) ----------
__device__ float g_h[NN * 128];      // pre-aggregation features (x @ W)
__device__ float g_agg[NN * 128];    // aggregated features
__device__ float g_deg[NN];
__device__ float g_dinv[NN];
__device__ int   g_cnt[NN];
__device__ int   g_cursor[NN];
__device__ int   g_rowptr[NN + 1];
__device__ int2  g_csr[EE];          // {src, __float_as_int(coef)}
// [0,256): layer1 sum/sumsq, [256,512): layer2 sum/sumsq,
// [512,768): layer1 scale/shift, [768,1024): layer2 scale/shift
__device__ float g_stats[1024];

// ---------------- CSR build ------------------------------------------------
__global__ void k_init() {
    int i = blockIdx.x * 256 + threadIdx.x;
    if (i < NN) { g_deg[i] = 1.0f; g_cnt[i] = 0; g_cursor[i] = 0; }
    if (i < 1024) g_stats[i] = 0.0f;
}

__global__ void k_count(const int* __restrict__ dst, const float* __restrict__ ew) {
    int e = blockIdx.x * 256 + threadIdx.x;
    if (e < EE) {
        int d = dst[e];
        atomicAdd(&g_cnt[d], 1);
        atomicAdd(&g_deg[d], ew[e]);
    }
}

__global__ void k_scan() {
    const int tid = threadIdx.x;
    __shared__ int warp_sums[32];
    __shared__ int s_carry;
    if (tid == 0) s_carry = 0;
    __syncthreads();
    for (int base = 0; base < NN; base += 1024) {
        int i = base + tid;
        int v = (i < NN) ? g_cnt[i] : 0;
        int x = v;
        #pragma unroll
        for (int o = 1; o < 32; o <<= 1) {
            int t = __shfl_up_sync(0xffffffffu, x, o);
            if ((tid & 31) >= o) x += t;
        }
        if ((tid & 31) == 31) warp_sums[tid >> 5] = x;
        __syncthreads();
        if (tid < 32) {
            int w = warp_sums[tid];
            #pragma unroll
            for (int o = 1; o < 32; o <<= 1) {
                int t = __shfl_up_sync(0xffffffffu, w, o);
                if (tid >= o) w += t;
            }
            warp_sums[tid] = w;
        }
        __syncthreads();
        int woff = (tid >= 32) ? warp_sums[(tid >> 5) - 1] : 0;
        int incl = x + woff;
        int carry = s_carry;
        if (i < NN) {
            g_rowptr[i] = carry + incl - v;   // exclusive
            g_dinv[i] = rsqrtf(g_deg[i]);     // deg >= 1 always (self loop)
        }
        __syncthreads();
        if (tid == 1023) s_carry = carry + incl;
        __syncthreads();
    }
    if (tid == 0) g_rowptr[NN] = s_carry;
}

__global__ void k_fill(const int* __restrict__ src, const int* __restrict__ dst,
                       const float* __restrict__ ew) {
    int e = blockIdx.x * 256 + threadIdx.x;
    if (e < EE) {
        int s = src[e], d = dst[e];
        int pos = g_rowptr[d] + atomicAdd(&g_cursor[d], 1);
        float c = g_dinv[s] * ew[e] * g_dinv[d];
        g_csr[pos] = make_int2(s, __float_as_int(c));
    }
}

// ---------------- GEMM: g_h = act(A) @ W  (K = 128 always) -----------------
// BN = output cols (128 or 64). If coff >= 0, applies fused
// relu(v * scale[k] + shift[k]) to A elements on load (BN+ReLU of prev layer).
// If Aext == nullptr, reads g_agg.
template <int BN>
__global__ void __launch_bounds__(256, 2)
k_gemm(const float* __restrict__ Aext, const float* __restrict__ Wm, int coff) {
    constexpr int CG = BN / 8;     // col groups (16 or 8)
    constexpr int RG = 256 / CG;   // row groups (16 or 32)
    constexpr int BM = RG * 8;     // tile rows (128 or 256)
    constexpr int BK = 16;
    __shared__ float As[BK][BM + 4];
    __shared__ float Bs[BK][BN];
    const float* A = Aext ? Aext : g_agg;
    const int tid = threadIdx.x;
    const int row_base = blockIdx.x * BM;
    const int rg = tid / CG, cg = tid % CG;

    float acc[8][8];
    #pragma unroll
    for (int i = 0; i < 8; i++)
        #pragma unroll
        for (int j = 0; j < 8; j++) acc[i][j] = 0.0f;

    for (int k0 = 0; k0 < 128; k0 += BK) {
        // load A tile (transposed into As[k][row]) with fused BN+ReLU
        #pragma unroll
        for (int i = tid; i < BM * 4; i += 256) {
            int r = i >> 2;
            int kk = (i & 3) << 2;
            int gr = row_base + r;
            float4 v = make_float4(0.f, 0.f, 0.f, 0.f);
            if (gr < NN) {
                v = *(const float4*)(A + gr * 128 + k0 + kk);
                if (coff >= 0) {
                    float4 sc = *(const float4*)(g_stats + coff + k0 + kk);
                    float4 sh = *(const float4*)(g_stats + coff + 128 + k0 + kk);
                    v.x = fmaxf(0.f, fmaf(v.x, sc.x, sh.x));
                    v.y = fmaxf(0.f, fmaf(v.y, sc.y, sh.y));
                    v.z = fmaxf(0.f, fmaf(v.z, sc.z, sh.z));
                    v.w = fmaxf(0.f, fmaf(v.w, sc.w, sh.w));
                }
            }
            As[kk + 0][r] = v.x; As[kk + 1][r] = v.y;
            As[kk + 2][r] = v.z; As[kk + 3][r] = v.w;
        }
        // load W tile
        #pragma unroll
        for (int i = tid; i < BK * (BN / 4); i += 256) {
            int kk = i / (BN / 4);
            int c = (i % (BN / 4)) << 2;
            *(float4*)&Bs[kk][c] = *(const float4*)(Wm + (k0 + kk) * BN + c);
        }
        __syncthreads();
        #pragma unroll
        for (int kk = 0; kk < BK; kk++) {
            float a[8], b[8];
            #pragma unroll
            for (int j = 0; j < 8; j++) a[j] = As[kk][rg * 8 + j];
            #pragma unroll
            for (int j = 0; j < 8; j++) b[j] = Bs[kk][cg * 8 + j];
            #pragma unroll
            for (int ii = 0; ii < 8; ii++)
                #pragma unroll
                for (int jj = 0; jj < 8; jj++)
                    acc[ii][jj] = fmaf(a[ii], b[jj], acc[ii][jj]);
        }
        __syncthreads();
    }
    #pragma unroll
    for (int ii = 0; ii < 8; ii++) {
        int gr = row_base + rg * 8 + ii;
        if (gr < NN) {
            float4 v0 = make_float4(acc[ii][0], acc[ii][1], acc[ii][2], acc[ii][3]);
            float4 v1 = make_float4(acc[ii][4], acc[ii][5], acc[ii][6], acc[ii][7]);
            *(float4*)(g_h + gr * BN + cg * 8) = v0;
            *(float4*)(g_h + gr * BN + cg * 8 + 4) = v1;
        }
    }
}

// ---------------- aggregation: out[n] = b + dinv[n]^2 h[n] + sum coef*h[src]
__global__ void __launch_bounds__(256)
k_agg128(const float* __restrict__ bias, float* __restrict__ outp) {
    int w = (blockIdx.x * 256 + threadIdx.x) >> 5;
    int lane = threadIdx.x & 31;
    if (w >= NN) return;
    const float4* h4 = (const float4*)g_h;
    float4 b4 = ((const float4*)bias)[lane];
    float4 sf = h4[w * 32 + lane];
    float di = g_dinv[w];
    float sc = di * di;
    float4 acc;
    acc.x = fmaf(sc, sf.x, b4.x);
    acc.y = fmaf(sc, sf.y, b4.y);
    acc.z = fmaf(sc, sf.z, b4.z);
    acc.w = fmaf(sc, sf.w, b4.w);
    int e = g_rowptr[w];
    const int end = g_rowptr[w + 1];
    for (; e + 2 <= end; e += 2) {
        int2 p0 = g_csr[e], p1 = g_csr[e + 1];
        float4 v0 = h4[p0.x * 32 + lane];
        float4 v1 = h4[p1.x * 32 + lane];
        float c0 = __int_as_float(p0.y), c1 = __int_as_float(p1.y);
        acc.x = fmaf(c0, v0.x, acc.x); acc.y = fmaf(c0, v0.y, acc.y);
        acc.z = fmaf(c0, v0.z, acc.z); acc.w = fmaf(c0, v0.w, acc.w);
        acc.x = fmaf(c1, v1.x, acc.x); acc.y = fmaf(c1, v1.y, acc.y);
        acc.z = fmaf(c1, v1.z, acc.z); acc.w = fmaf(c1, v1.w, acc.w);
    }
    if (e < end) {
        int2 p = g_csr[e];
        float4 v = h4[p.x * 32 + lane];
        float c = __int_as_float(p.y);
        acc.x = fmaf(c, v.x, acc.x); acc.y = fmaf(c, v.y, acc.y);
        acc.z = fmaf(c, v.z, acc.z); acc.w = fmaf(c, v.w, acc.w);
    }
    float4* o4 = (float4*)(outp ? outp : g_agg);
    o4[w * 32 + lane] = acc;
}

__global__ void __launch_bounds__(256)
k_agg64(const float* __restrict__ bias, float* __restrict__ outp) {
    int w = (blockIdx.x * 256 + threadIdx.x) >> 5;
    int lane = threadIdx.x & 31;
    if (w >= NN) return;
    const float2* h2 = (const float2*)g_h;   // g_h interpreted as [NN][64]
    float2 b2v = ((const float2*)bias)[lane];
    float2 sf = h2[w * 32 + lane];
    float di = g_dinv[w];
    float sc = di * di;
    float2 acc;
    acc.x = fmaf(sc, sf.x, b2v.x);
    acc.y = fmaf(sc, sf.y, b2v.y);
    int e = g_rowptr[w];
    const int end = g_rowptr[w + 1];
    for (; e + 2 <= end; e += 2) {
        int2 p0 = g_csr[e], p1 = g_csr[e + 1];
        float2 v0 = h2[p0.x * 32 + lane];
        float2 v1 = h2[p1.x * 32 + lane];
        float c0 = __int_as_float(p0.y), c1 = __int_as_float(p1.y);
        acc.x = fmaf(c0, v0.x, acc.x); acc.y = fmaf(c0, v0.y, acc.y);
        acc.x = fmaf(c1, v1.x, acc.x); acc.y = fmaf(c1, v1.y, acc.y);
    }
    if (e < end) {
        int2 p = g_csr[e];
        float2 v = h2[p.x * 32 + lane];
        float c = __int_as_float(p.y);
        acc.x = fmaf(c, v.x, acc.x); acc.y = fmaf(c, v.y, acc.y);
    }
    ((float2*)outp)[w * 32 + lane] = acc;
}

// ---------------- BN stats + finalize --------------------------------------
__global__ void k_bnstats(int off) {
    int col = threadIdx.x;                    // 128 threads
    float s = 0.f, s2 = 0.f;
    for (int r = blockIdx.x; r < NN; r += gridDim.x) {
        float v = g_agg[r * 128 + col];
        s += v; s2 += v * v;
    }
    atomicAdd(&g_stats[off + col], s);
    atomicAdd(&g_stats[off + 128 + col], s2);
}

__global__ void k_bnfin(int soff, int coff, const float* __restrict__ gamma,
                        const float* __restrict__ beta) {
    int c = threadIdx.x;
    if (c < 128) {
        float mean = g_stats[soff + c] * (1.0f / NN);
        float var = g_stats[soff + 128 + c] * (1.0f / NN) - mean * mean;
        float rstd = rsqrtf(var + 1e-5f);
        float sc = rstd * gamma[c];
        g_stats[coff + c] = sc;
        g_stats[coff + 128 + c] = beta[c] - mean * sc;
    }
}

// ---------------- launch ----------------------------------------------------
extern "C" void kernel_launch(void* const* d_in, const int* in_sizes, int n_in,
                              void* d_out, int out_size) {
    const float* x   = (const float*)d_in[0];
    const int*   ei  = (const int*)d_in[1];
    const float* ew  = (const float*)d_in[2];
    const float* W1  = (const float*)d_in[3];
    const float* b1  = (const float*)d_in[4];
    const float* W2  = (const float*)d_in[5];
    const float* b2  = (const float*)d_in[6];
    const float* W3  = (const float*)d_in[7];
    const float* b3  = (const float*)d_in[8];
    const float* g1  = (const float*)d_in[9];
    const float* be1 = (const float*)d_in[10];
    const float* g2  = (const float*)d_in[11];
    const float* be2 = (const float*)d_in[12];
    const int* src = ei;
    const int* dst = ei + EE;
    float* out = (float*)d_out;

    const int agg_blocks = (NN * 32 + 255) / 256;

    // graph normalization + CSR (shared by all 3 layers)
    k_init<<<(NN + 255) / 256, 256>>>();
    k_count<<<(EE + 255) / 256, 256>>>(dst, ew);
    k_scan<<<1, 1024>>>();
    k_fill<<<(EE + 255) / 256, 256>>>(src, dst, ew);

    // layer 1
    k_gemm<128><<<(NN + 127) / 128, 256>>>(x, W1, -1);
    k_agg128<<<agg_blocks, 256>>>(b1, nullptr);
    k_bnstats<<<592, 128>>>(0);
    k_bnfin<<<1, 128>>>(0, 512, g1, be1);

    // layer 2 (BN+ReLU of layer1 fused into A-load)
    k_gemm<128><<<(NN + 127) / 128, 256>>>(nullptr, W2, 512);
    k_agg128<<<agg_blocks, 256>>>(b2, nullptr);
    k_bnstats<<<592, 128>>>(256);
    k_bnfin<<<1, 128>>>(256, 768, g2, be2);

    // layer 3 (64-wide output; BN+ReLU of layer2 fused into A-load)
    k_gemm<64><<<(NN + 255) / 256, 256>>>(nullptr, W3, 768);
    k_agg64<<<agg_blocks, 256>>>(b3, out);
}

// round 4
// speedup vs baseline: 1.0791x; 1.0791x over previous
#include <cuda_runtime.h>

static constexpr int NN = 50000;
static constexpr int EE = 800000;

typedef unsigned long long u64;

__device__ __forceinline__ u64 fma2(u64 a, u64 b, u64 c) {
    u64 d;
    asm("fma.rn.f32x2 %0, %1, %2, %3;" : "=l"(d) : "l"(a), "l"(b), "l"(c));
    return d;
}
__device__ __forceinline__ float2 unpack2(u64 v) {
    float2 f;
    asm("mov.b64 {%0,%1}, %2;" : "=f"(f.x), "=f"(f.y) : "l"(v));
    return f;
}

// ---------------- scratch (device globals; no allocation allowed) ----------
__device__ float g_h[NN * 128];      // pre-aggregation features (act(A) @ W)
__device__ float g_agg[NN * 128];    // aggregated features
__device__ float g_deg[NN];
__device__ float g_dinv[NN];
__device__ int   g_cnt[NN];
__device__ int   g_cursor[NN];
__device__ int   g_rowptr[NN + 1];
__device__ int2  g_csr[EE];          // {src, __float_as_int(coef)}
// [0,256): layer1 sum/sumsq, [256,512): layer2 sum/sumsq,
// [512,768): layer1 scale/shift, [768,1024): layer2 scale/shift
__device__ float g_stats[1024];

// ---------------- CSR build ------------------------------------------------
__global__ void k_init() {
    int i = blockIdx.x * 256 + threadIdx.x;
    if (i < NN) { g_deg[i] = 1.0f; g_cnt[i] = 0; g_cursor[i] = 0; }
    if (i < 1024) g_stats[i] = 0.0f;
}

__global__ void k_count(const int* __restrict__ dst, const float* __restrict__ ew) {
    int e = blockIdx.x * 256 + threadIdx.x;
    const int H = EE / 2;
    if (e < H) {
        int d0 = dst[e];
        int d1 = dst[e + H];
        float w0 = ew[e];
        float w1 = ew[e + H];
        atomicAdd(&g_cnt[d0], 1);
        atomicAdd(&g_deg[d0], w0);
        atomicAdd(&g_cnt[d1], 1);
        atomicAdd(&g_deg[d1], w1);
    }
}

__global__ void k_scan() {
    const int tid = threadIdx.x;
    __shared__ int warp_sums[32];
    __shared__ int s_carry;
    if (tid == 0) s_carry = 0;
    __syncthreads();
    for (int base = 0; base < NN; base += 1024) {
        int i = base + tid;
        int v = (i < NN) ? g_cnt[i] : 0;
        int x = v;
        #pragma unroll
        for (int o = 1; o < 32; o <<= 1) {
            int t = __shfl_up_sync(0xffffffffu, x, o);
            if ((tid & 31) >= o) x += t;
        }
        if ((tid & 31) == 31) warp_sums[tid >> 5] = x;
        __syncthreads();
        if (tid < 32) {
            int w = warp_sums[tid];
            #pragma unroll
            for (int o = 1; o < 32; o <<= 1) {
                int t = __shfl_up_sync(0xffffffffu, w, o);
                if (tid >= o) w += t;
            }
            warp_sums[tid] = w;
        }
        __syncthreads();
        int woff = (tid >= 32) ? warp_sums[(tid >> 5) - 1] : 0;
        int incl = x + woff;
        int carry = s_carry;
        if (i < NN) {
            g_rowptr[i] = carry + incl - v;   // exclusive
            g_dinv[i] = rsqrtf(g_deg[i]);     // deg >= 1 always (self loop)
        }
        __syncthreads();
        if (tid == 1023) s_carry = carry + incl;
        __syncthreads();
    }
    if (tid == 0) g_rowptr[NN] = s_carry;
}

__global__ void k_fill(const int* __restrict__ src, const int* __restrict__ dst,
                       const float* __restrict__ ew) {
    int e = blockIdx.x * 256 + threadIdx.x;
    const int H = EE / 2;
    if (e < H) {
        int s0 = src[e],     d0 = dst[e];
        int s1 = src[e + H], d1 = dst[e + H];
        float w0 = ew[e], w1 = ew[e + H];
        float ds0 = g_dinv[s0], dd0 = g_dinv[d0];
        float ds1 = g_dinv[s1], dd1 = g_dinv[d1];
        int rp0 = g_rowptr[d0];
        int rp1 = g_rowptr[d1];
        int p0 = rp0 + atomicAdd(&g_cursor[d0], 1);
        int p1 = rp1 + atomicAdd(&g_cursor[d1], 1);
        g_csr[p0] = make_int2(s0, __float_as_int(ds0 * w0 * dd0));
        g_csr[p1] = make_int2(s1, __float_as_int(ds1 * w1 * dd1));
    }
}

// ---------------- GEMM: g_h = act(A) @ W  (K = 128, packed f32x2) ----------
// If coff >= 0, applies relu(v*scale+shift) to A on load (prev layer BN+ReLU).
// If Aext == nullptr, reads g_agg.
template <int BN>
__global__ void __launch_bounds__(256, 2)
k_gemm(const float* __restrict__ Aext, const float* __restrict__ Wm, int coff) {
    constexpr int CG = BN / 8;     // col groups (16 or 8)
    constexpr int RG = 256 / CG;   // row groups (16 or 32)
    constexpr int BM = RG * 8;     // tile rows (128 or 256)
    constexpr int BK = 16;
    __shared__ float  As[BK][BM + 4];
    __shared__ float2 Bs2[BK][8][CG];   // [k][j][cg], value duplicated {b,b}
    const float* A = Aext ? Aext : g_agg;
    const int tid = threadIdx.x;
    const int row_base = blockIdx.x * BM;
    const int rg = tid / CG, cg = tid % CG;

    u64 acc[4][8];   // [row-pair][col]; rows rg*8+2i, rg*8+2i+1; col cg*8+j
    #pragma unroll
    for (int i = 0; i < 4; i++)
        #pragma unroll
        for (int j = 0; j < 8; j++) acc[i][j] = 0ull;

    for (int k0 = 0; k0 < 128; k0 += BK) {
        // A tile (transposed into As[k][row]) with fused BN+ReLU
        #pragma unroll
        for (int i = tid; i < BM * 4; i += 256) {
            int r = i >> 2;
            int kk = (i & 3) << 2;
            int gr = row_base + r;
            float4 v = make_float4(0.f, 0.f, 0.f, 0.f);
            if (gr < NN) {
                v = *(const float4*)(A + gr * 128 + k0 + kk);
                if (coff >= 0) {
                    float4 sc = *(const float4*)(g_stats + coff + k0 + kk);
                    float4 sh = *(const float4*)(g_stats + coff + 128 + k0 + kk);
                    v.x = fmaxf(0.f, fmaf(v.x, sc.x, sh.x));
                    v.y = fmaxf(0.f, fmaf(v.y, sc.y, sh.y));
                    v.z = fmaxf(0.f, fmaf(v.z, sc.z, sh.z));
                    v.w = fmaxf(0.f, fmaf(v.w, sc.w, sh.w));
                }
            }
            As[kk + 0][r] = v.x; As[kk + 1][r] = v.y;
            As[kk + 2][r] = v.z; As[kk + 3][r] = v.w;
        }
        // W tile, duplicated into Bs2[kk][j][cg]
        #pragma unroll
        for (int i = tid; i < BK * (BN / 4); i += 256) {
            int kk = i / (BN / 4);
            int c = (i % (BN / 4)) << 2;   // multiple of 4
            float4 wv = *(const float4*)(Wm + (k0 + kk) * BN + c);
            int jb = c & 7, cc = c >> 3;
            Bs2[kk][jb + 0][cc] = make_float2(wv.x, wv.x);
            Bs2[kk][jb + 1][cc] = make_float2(wv.y, wv.y);
            Bs2[kk][jb + 2][cc] = make_float2(wv.z, wv.z);
            Bs2[kk][jb + 3][cc] = make_float2(wv.w, wv.w);
        }
        __syncthreads();
        #pragma unroll
        for (int kk = 0; kk < BK; kk++) {
            u64 a2[4], b2[8];
            #pragma unroll
            for (int i = 0; i < 4; i++)
                a2[i] = *(const u64*)&As[kk][rg * 8 + 2 * i];
            #pragma unroll
            for (int j = 0; j < 8; j++)
                b2[j] = *(const u64*)&Bs2[kk][j][cg];
            #pragma unroll
            for (int i = 0; i < 4; i++)
                #pragma unroll
                for (int j = 0; j < 8; j++)
                    acc[i][j] = fma2(a2[i], b2[j], acc[i][j]);
        }
        __syncthreads();
    }
    #pragma unroll
    for (int i = 0; i < 4; i++) {
        int r0 = row_base + rg * 8 + 2 * i;
        float lo[8], hi[8];
        #pragma unroll
        for (int j = 0; j < 8; j++) {
            float2 v = unpack2(acc[i][j]);
            lo[j] = v.x; hi[j] = v.y;
        }
        if (r0 < NN) {
            *(float4*)(g_h + r0 * BN + cg * 8)     = make_float4(lo[0], lo[1], lo[2], lo[3]);
            *(float4*)(g_h + r0 * BN + cg * 8 + 4) = make_float4(lo[4], lo[5], lo[6], lo[7]);
        }
        if (r0 + 1 < NN) {
            *(float4*)(g_h + (r0 + 1) * BN + cg * 8)     = make_float4(hi[0], hi[1], hi[2], hi[3]);
            *(float4*)(g_h + (r0 + 1) * BN + cg * 8 + 4) = make_float4(hi[4], hi[5], hi[6], hi[7]);
        }
    }
}

// ---------------- aggregation + fused BN stats -----------------------------
// out[n] = b + dinv[n]^2 h[n] + sum coef*h[src]; if statsoff>=0 also
// accumulates per-column sum/sumsq of the output into g_stats[statsoff..].
__global__ void __launch_bounds__(256)
k_agg128(const float* __restrict__ bias, float* __restrict__ outp, int statsoff) {
    __shared__ float4 s_sum[8][32];
    __shared__ float4 s_sq[8][32];
    int wlocal = threadIdx.x >> 5;
    int w = (blockIdx.x * 256 + threadIdx.x) >> 5;
    int lane = threadIdx.x & 31;
    const float4* h4 = (const float4*)g_h;
    float4 b4 = ((const float4*)bias)[lane];
    float4 sf = h4[w * 32 + lane];
    float di = g_dinv[w];
    float sc = di * di;
    float4 acc;
    acc.x = fmaf(sc, sf.x, b4.x);
    acc.y = fmaf(sc, sf.y, b4.y);
    acc.z = fmaf(sc, sf.z, b4.z);
    acc.w = fmaf(sc, sf.w, b4.w);
    int e = g_rowptr[w];
    const int end = g_rowptr[w + 1];
    for (; e + 2 <= end; e += 2) {
        int2 p0 = g_csr[e], p1 = g_csr[e + 1];
        float4 v0 = h4[p0.x * 32 + lane];
        float4 v1 = h4[p1.x * 32 + lane];
        float c0 = __int_as_float(p0.y), c1 = __int_as_float(p1.y);
        acc.x = fmaf(c0, v0.x, acc.x); acc.y = fmaf(c0, v0.y, acc.y);
        acc.z = fmaf(c0, v0.z, acc.z); acc.w = fmaf(c0, v0.w, acc.w);
        acc.x = fmaf(c1, v1.x, acc.x); acc.y = fmaf(c1, v1.y, acc.y);
        acc.z = fmaf(c1, v1.z, acc.z); acc.w = fmaf(c1, v1.w, acc.w);
    }
    if (e < end) {
        int2 p = g_csr[e];
        float4 v = h4[p.x * 32 + lane];
        float c = __int_as_float(p.y);
        acc.x = fmaf(c, v.x, acc.x); acc.y = fmaf(c, v.y, acc.y);
        acc.z = fmaf(c, v.z, acc.z); acc.w = fmaf(c, v.w, acc.w);
    }
    float4* o4 = (float4*)(outp ? outp : g_agg);
    o4[w * 32 + lane] = acc;

    if (statsoff >= 0) {
        s_sum[wlocal][lane] = acc;
        s_sq[wlocal][lane] = make_float4(acc.x * acc.x, acc.y * acc.y,
                                         acc.z * acc.z, acc.w * acc.w);
        __syncthreads();
        if (threadIdx.x < 128) {
            int c = threadIdx.x;         // column 0..127
            int l = c >> 2, comp = c & 3;
            float s = 0.f, q = 0.f;
            #pragma unroll
            for (int ww = 0; ww < 8; ww++) {
                const float* ps = (const float*)&s_sum[ww][l];
                const float* pq = (const float*)&s_sq[ww][l];
                s += ps[comp];
                q += pq[comp];
            }
            atomicAdd(&g_stats[statsoff + c], s);
            atomicAdd(&g_stats[statsoff + 128 + c], q);
        }
    }
}

__global__ void __launch_bounds__(256)
k_agg64(const float* __restrict__ bias, float* __restrict__ outp) {
    int w = (blockIdx.x * 256 + threadIdx.x) >> 5;
    int lane = threadIdx.x & 31;
    const float2* h2 = (const float2*)g_h;   // g_h interpreted as [NN][64]
    float2 b2v = ((const float2*)bias)[lane];
    float2 sf = h2[w * 32 + lane];
    float di = g_dinv[w];
    float sc = di * di;
    float2 acc;
    acc.x = fmaf(sc, sf.x, b2v.x);
    acc.y = fmaf(sc, sf.y, b2v.y);
    int e = g_rowptr[w];
    const int end = g_rowptr[w + 1];
    for (; e + 2 <= end; e += 2) {
        int2 p0 = g_csr[e], p1 = g_csr[e + 1];
        float2 v0 = h2[p0.x * 32 + lane];
        float2 v1 = h2[p1.x * 32 + lane];
        float c0 = __int_as_float(p0.y), c1 = __int_as_float(p1.y);
        acc.x = fmaf(c0, v0.x, acc.x); acc.y = fmaf(c0, v0.y, acc.y);
        acc.x = fmaf(c1, v1.x, acc.x); acc.y = fmaf(c1, v1.y, acc.y);
    }
    if (e < end) {
        int2 p = g_csr[e];
        float2 v = h2[p.x * 32 + lane];
        float c = __int_as_float(p.y);
        acc.x = fmaf(c, v.x, acc.x); acc.y = fmaf(c, v.y, acc.y);
    }
    ((float2*)outp)[w * 32 + lane] = acc;
}

// ---------------- BN finalize ----------------------------------------------
__global__ void k_bnfin(int soff, int coff, const float* __restrict__ gamma,
                        const float* __restrict__ beta) {
    int c = threadIdx.x;
    if (c < 128) {
        float mean = g_stats[soff + c] * (1.0f / NN);
        float var = g_stats[soff + 128 + c] * (1.0f / NN) - mean * mean;
        float rstd = rsqrtf(var + 1e-5f);
        float sc = rstd * gamma[c];
        g_stats[coff + c] = sc;
        g_stats[coff + 128 + c] = beta[c] - mean * sc;
    }
}

// ---------------- launch ----------------------------------------------------
extern "C" void kernel_launch(void* const* d_in, const int* in_sizes, int n_in,
                              void* d_out, int out_size) {
    const float* x   = (const float*)d_in[0];
    const int*   ei  = (const int*)d_in[1];
    const float* ew  = (const float*)d_in[2];
    const float* W1  = (const float*)d_in[3];
    const float* b1  = (const float*)d_in[4];
    const float* W2  = (const float*)d_in[5];
    const float* b2  = (const float*)d_in[6];
    const float* W3  = (const float*)d_in[7];
    const float* b3  = (const float*)d_in[8];
    const float* g1  = (const float*)d_in[9];
    const float* be1 = (const float*)d_in[10];
    const float* g2  = (const float*)d_in[11];
    const float* be2 = (const float*)d_in[12];
    const int* src = ei;
    const int* dst = ei + EE;
    float* out = (float*)d_out;

    const int agg_blocks = (NN * 32) / 256;           // 6250 exact
    const int half_blocks = (EE / 2 + 255) / 256;     // 1563

    // graph normalization + CSR (shared by all 3 layers)
    k_init<<<(NN + 255) / 256, 256>>>();
    k_count<<<half_blocks, 256>>>(dst, ew);
    k_scan<<<1, 1024>>>();
    k_fill<<<half_blocks, 256>>>(src, dst, ew);

    // layer 1
    k_gemm<128><<<(NN + 127) / 128, 256>>>(x, W1, -1);
    k_agg128<<<agg_blocks, 256>>>(b1, nullptr, 0);
    k_bnfin<<<1, 128>>>(0, 512, g1, be1);

    // layer 2 (BN+ReLU of layer1 fused into A-load)
    k_gemm<128><<<(NN + 127) / 128, 256>>>(nullptr, W2, 512);
    k_agg128<<<agg_blocks, 256>>>(b2, nullptr, 256);
    k_bnfin<<<1, 128>>>(256, 768, g2, be2);

    // layer 3 (64-wide output; BN+ReLU of layer2 fused into A-load)
    k_gemm<64><<<(NN + 255) / 256, 256>>>(nullptr, W3, 768);
    k_agg64<<<agg_blocks, 256>>>(b3, out);
}